// round 8
// baseline (speedup 1.0000x reference)
#include <cuda_runtime.h>
#include <cuda_bf16.h>
#include <cstdint>

#define BSZ   8
#define NROI  64
#define HDIM  512
#define NLAYER 5
#define BI    (BSZ*NROI)                     // 512 (b,i) pairs

// ---------------- scratch (device globals; no allocation allowed) ----------
__device__ int8_t g_q8[2][(size_t)BSZ*NROI*NROI*HDIM];  // ping-pong edge_state (int8, x16)
__device__ int8_t g_eW8[(size_t)4*HDIM*HDIM];           // int8 edge weights (layers 1..4)
__device__ float  g_wsEff[4*HDIM];                      // per-o-row scale: rowmax/(127*16)
__device__ __nv_bfloat16 g_nW16[(size_t)NLAYER*HDIM*HDIM];  // bf16 node weights
__device__ __nv_bfloat16 g_ns16[BI*HDIM];               // bf16 mirror of node_state
__device__ float g_nm[BI*HDIM];
__device__ float g_ns[BI*HDIM];
__device__ float g_denom[BI];
__device__ float g_em0[BSZ*HDIM];                       // layer-0 edge matvec (incl. bias)
__device__ float g_e0[BSZ*HDIM];                        // mean of img_featmap

__device__ __forceinline__ float leaky(float x) { return x >= 0.f ? x : 0.01f * x; }
__device__ __forceinline__ unsigned smem_u32(const void* p) {
    return (unsigned)__cvta_generic_to_shared(p);
}
__device__ __forceinline__ void cpa16(unsigned dst, const void* src) {
    asm volatile("cp.async.ca.shared.global [%0], [%1], 16;" :: "r"(dst), "l"(src));
}
__device__ __forceinline__ int q8clamp(float v) {
    return __float2int_rn(fminf(fmaxf(v, -127.f), 127.f));
}

// ---------------- prep: node_state copy (+bf16), e0 mean, denom -------------
__global__ void prep_kernel(const float* __restrict__ roi,
                            const float* __restrict__ img,
                            const int*  __restrict__ mask) {
    int idx = blockIdx.x * blockDim.x + threadIdx.x;
    int total = blockDim.x * gridDim.x;
    for (int i = idx; i < BI*HDIM; i += total) {
        float v = roi[i];
        g_ns[i] = v;
        g_ns16[i] = __float2bfloat16(v);
    }
    if (idx < BSZ*HDIM) {
        const float* p = img + (size_t)idx * 196;
        float s = 0.f;
        #pragma unroll 4
        for (int q = 0; q < 196; q++) s += p[q];
        g_e0[idx] = s * (1.0f/196.0f);
    }
    if (idx < BI) {
        const int* m = mask + idx * NROI;
        int s = 0;
        #pragma unroll
        for (int j = 0; j < NROI; j++) s += m[j];
        g_denom[idx] = (float)s + 1.0f;
    }
}

// ---------------- convert node weights to bf16 -------------------------------
__global__ void convW_kernel(const float* __restrict__ nW) {
    int i = blockIdx.x * blockDim.x + threadIdx.x;
    if (i < NLAYER*HDIM*HDIM/2) {
        float2 v = ((const float2*)nW)[i];
        ((__nv_bfloat162*)g_nW16)[i] = __floats2bfloat162_rn(v.x, v.y);
    }
}

// ---------------- quantize edge weights (layers 1..4) to int8 ----------------
// One warp per output row o: rowmax -> scale -> 512 q8 + wsEff = sw/16.
__global__ void quantW_kernel(const float* __restrict__ eW) {
    int r = (blockIdx.x * blockDim.x + threadIdx.x) >> 5;   // 0..2047
    int lane = threadIdx.x & 31;
    if (r >= 4*HDIM) return;
    int t = (r >> 9) + 1;                   // layer 1..4
    int o = r & 511;
    const float* w = eW + (size_t)t*HDIM*HDIM + (size_t)o*HDIM;
    float mx = 0.f;
    float4 v[4];
    #pragma unroll
    for (int q = 0; q < 4; q++) {
        v[q] = ((const float4*)w)[lane + q*32];
        mx = fmaxf(mx, fmaxf(fmaxf(fabsf(v[q].x), fabsf(v[q].y)),
                             fmaxf(fabsf(v[q].z), fabsf(v[q].w))));
    }
    #pragma unroll
    for (int d = 16; d; d >>= 1) mx = fmaxf(mx, __shfl_xor_sync(0xffffffffu, mx, d));
    float sw = mx / 127.f + 1e-30f;
    float inv = 1.f / sw;
    // each lane packs its 16 values (4 words)
    uint32_t pk[4];
    #pragma unroll
    for (int q = 0; q < 4; q++) {
        int q0 = q8clamp(v[q].x * inv) & 0xFF;
        int q1 = q8clamp(v[q].y * inv) & 0xFF;
        int q2 = q8clamp(v[q].z * inv) & 0xFF;
        int q3 = q8clamp(v[q].w * inv) & 0xFF;
        pk[q] = (uint32_t)(q0 | (q1 << 8) | (q2 << 16) | (q3 << 24));
    }
    // lane's 16 bytes are at columns lane*4 + q*128 (float4 stride 32*4)
    int8_t* dst = g_eW8 + (size_t)(r) * HDIM;
    #pragma unroll
    for (int q = 0; q < 4; q++)
        *(uint32_t*)(dst + lane*4 + q*128) = pk[q];
    if (lane == 0) g_wsEff[r] = sw * (1.f/16.f);
}

// ---------------- layer-0 edge matvec (float4 vectorized) -------------------
__global__ void em0_kernel(const float* __restrict__ W0,
                           const float* __restrict__ eb0) {
    int warp = (blockIdx.x * blockDim.x + threadIdx.x) >> 5;
    int lane = threadIdx.x & 31;
    if (warp >= BSZ*HDIM) return;
    int b = warp >> 9;
    int o = warp & 511;
    const float4* e4 = (const float4*)(g_e0 + b*HDIM);
    const float4* w4 = (const float4*)(W0 + (size_t)o*HDIM);
    float s = 0.f;
    #pragma unroll
    for (int it = 0; it < 4; it++) {
        float4 e = e4[lane + it*32];
        float4 w = w4[lane + it*32];
        s += e.x*w.x + e.y*w.y + e.z*w.z + e.w*w.w;
    }
    #pragma unroll
    for (int d = 16; d; d >>= 1) s += __shfl_xor_sync(0xffffffffu, s, d);
    if (lane == 0) g_em0[warp] = s + eb0[o];
}

// ---------------- layer-0 fused edge (no GEMM) + node update ----------------
__global__ void edge0_kernel(const int* __restrict__ mask) {
    int bi = blockIdx.x;
    int b  = bi >> 6;
    const float* nmB = g_nm + (size_t)b * NROI * HDIM;
    const float* nmi = g_nm + (size_t)bi * HDIM;
    int8_t* dstp = g_q8[0] + (size_t)bi * NROI * HDIM;
    int o = threadIdx.x * 2;                 // pair of adjacent o
    float2 nmv = *(const float2*)(nmi + o);
    float2 em2 = *(const float2*)(g_em0 + b*HDIM + o);
    float base0 = nmv.x + em2.x, base1 = nmv.y + em2.y;
    float agg0 = 0.f, agg1 = 0.f;
    for (int j = 0; j < NROI; j++) {
        float m = (float)mask[bi*NROI + j];
        float2 nj = *(const float2*)(nmB + j*HDIM + o);
        float e0 = leaky(base0 + nj.x);
        float e1 = leaky(base1 + nj.y);
        int q0 = q8clamp(e0 * 16.f) & 0xFF;
        int q1 = q8clamp(e1 * 16.f) & 0xFF;
        *(unsigned short*)(dstp + j*HDIM + o) = (unsigned short)(q0 | (q1 << 8));
        agg0 += e0 * nj.x * m;
        agg1 += e1 * nj.y * m;
    }
    float dn = g_denom[bi];
    float ns0 = g_ns[(size_t)bi*HDIM + o]     + leaky((nmv.x + agg0) / dn);
    float ns1 = g_ns[(size_t)bi*HDIM + o + 1] + leaky((nmv.y + agg1) / dn);
    g_ns[(size_t)bi*HDIM + o]     = ns0;
    g_ns[(size_t)bi*HDIM + o + 1] = ns1;
    g_ns16[(size_t)bi*HDIM + o]     = __float2bfloat16(ns0);
    g_ns16[(size_t)bi*HDIM + o + 1] = __float2bfloat16(ns1);
}

// ======================= nm GEMM (bf16 mma.sync, unchanged) =================
#define KC    32
#define NIT   (HDIM/KC)     // 16
#define STRD  40

__global__ __launch_bounds__(256) void nm_mma_kernel(
    int t, const float* __restrict__ bt)
{
    __shared__ __nv_bfloat16 As[2][64*STRD];
    __shared__ __nv_bfloat16 Bs[2][128*STRD];

    int tid  = threadIdx.x;
    int wid  = tid >> 5, lane = tid & 31;
    int wm   = wid & 3, wn = wid >> 2;
    int r0   = blockIdx.y * 64;
    int o0   = blockIdx.x * 128;

    const __nv_bfloat16* A  = g_ns16 + (size_t)r0 * HDIM;
    const __nv_bfloat16* Bw = g_nW16 + (size_t)t * HDIM * HDIM + (size_t)o0 * HDIM;

    float acc[8][4] = {};

    int arow = tid >> 2, acol = (tid & 3) * 8;
    int brow = tid >> 1, bcol = (tid & 1) * 16;

    {
        cpa16(smem_u32(&As[0][arow*STRD + acol]), A + (size_t)arow*HDIM + acol);
        unsigned sB = smem_u32(&Bs[0][brow*STRD + bcol]);
        const __nv_bfloat16* gB = Bw + (size_t)brow*HDIM + bcol;
        cpa16(sB, gB); cpa16(sB+16, gB+8);
        asm volatile("cp.async.commit_group;");
    }

    for (int it = 0; it < NIT; it++) {
        asm volatile("cp.async.wait_group 0;");
        __syncthreads();
        if (it + 1 < NIT) {
            int st = (it + 1) & 1;
            int k0 = (it + 1) * KC;
            cpa16(smem_u32(&As[st][arow*STRD + acol]), A + (size_t)arow*HDIM + k0 + acol);
            unsigned sB = smem_u32(&Bs[st][brow*STRD + bcol]);
            const __nv_bfloat16* gB = Bw + (size_t)brow*HDIM + k0 + bcol;
            cpa16(sB, gB); cpa16(sB+16, gB+8);
            asm volatile("cp.async.commit_group;");
        }
        int st = it & 1;
        unsigned aBase = smem_u32(&As[st][(wm*16 + (lane & 15))*STRD + (lane >> 4)*8]);
        unsigned bBase = smem_u32(&Bs[st][(wn*64 + ((lane >> 4) << 3) + (lane & 7))*STRD
                                          + (((lane >> 3) & 1) << 3)]);
        #pragma unroll
        for (int ks = 0; ks < KC; ks += 16) {
            unsigned a0,a1,a2,a3;
            asm volatile("ldmatrix.sync.aligned.m8n8.x4.shared.b16 {%0,%1,%2,%3},[%4];"
                : "=r"(a0),"=r"(a1),"=r"(a2),"=r"(a3) : "r"(aBase + (unsigned)(ks*2)));
            #pragma unroll
            for (int p2 = 0; p2 < 4; p2++) {
                unsigned b0,b1,b2,b3;
                asm volatile("ldmatrix.sync.aligned.m8n8.x4.shared.b16 {%0,%1,%2,%3},[%4];"
                    : "=r"(b0),"=r"(b1),"=r"(b2),"=r"(b3)
                    : "r"(bBase + (unsigned)((p2*16*STRD + ks) * 2)));
                float* c0 = acc[p2*2];
                asm volatile("mma.sync.aligned.m16n8k16.row.col.f32.bf16.bf16.f32 "
                    "{%0,%1,%2,%3},{%4,%5,%6,%7},{%8,%9},{%0,%1,%2,%3};"
                    : "+f"(c0[0]),"+f"(c0[1]),"+f"(c0[2]),"+f"(c0[3])
                    : "r"(a0),"r"(a1),"r"(a2),"r"(a3),"r"(b0),"r"(b1));
                float* c1 = acc[p2*2+1];
                asm volatile("mma.sync.aligned.m16n8k16.row.col.f32.bf16.bf16.f32 "
                    "{%0,%1,%2,%3},{%4,%5,%6,%7},{%8,%9},{%0,%1,%2,%3};"
                    : "+f"(c1[0]),"+f"(c1[1]),"+f"(c1[2]),"+f"(c1[3])
                    : "r"(a0),"r"(a1),"r"(a2),"r"(a3),"r"(b2),"r"(b3));
            }
        }
        __syncthreads();
    }

    int r1 = r0 + wm*16 + (lane >> 2);
    int r2 = r1 + 8;
    #pragma unroll
    for (int p = 0; p < 8; p++) {
        int o = o0 + wn*64 + p*8 + (lane & 3)*2;
        float2 bo = *(const float2*)(bt + o);
        float2 v1; v1.x = acc[p][0] + bo.x; v1.y = acc[p][1] + bo.y;
        float2 v2; v2.x = acc[p][2] + bo.x; v2.y = acc[p][3] + bo.y;
        *(float2*)(g_nm + (size_t)r1*HDIM + o) = v1;
        *(float2*)(g_nm + (size_t)r2*HDIM + o) = v2;
    }
}

// ===== fused edge GEMM (layers 1..4): persistent-weight INT8 mma.sync =======
// Grid (4 o-tiles, 37 bi-groups) = 148 blocks. Resident: B int8 tile 128x512,
// per-b nm smem tile (64 x 128 floats). A int8 (64x512) double-buffered.
// mma.sync.m16n8k32.s8.s8.s32 -> 2x MACs per instruction vs bf16.
#define QSTR  528                      // smem row stride BYTES (16-aligned, %128==16)
#define SM_B8 (128*QSTR)               // 67584
#define SM_A8 (64*QSTR)                // 33792
#define SM_NM (64*QSTR)                // 64 rows x 132 floats = 33792
#define EDSM8 (SM_B8 + 2*SM_A8 + SM_NM)  // 168960

__global__ __launch_bounds__(256) void edge_q8_kernel(
    int t, const float* __restrict__ ebt, const int* __restrict__ mask,
    int src, int dst, int writeEdge)
{
    extern __shared__ __align__(16) unsigned char dsm[];
    __shared__ float aggsm[4][128];

    unsigned dB  = smem_u32(dsm);
    unsigned dA0 = dB + SM_B8;
    unsigned dA1 = dA0 + SM_A8;
    unsigned dNM = dA1 + SM_A8;

    int tid  = threadIdx.x;
    int wid  = tid >> 5, lane = tid & 31;
    int wm   = wid & 3, wn = wid >> 2;
    int o0   = blockIdx.x * 128;
    int g    = blockIdx.y;             // 0..36
    int myStart = (g < 31) ? g*14 : 434 + (g-31)*13;
    int myCount = (g < 31) ? 14 : 13;

    const int8_t* Bw8 = g_eW8 + (size_t)(t-1)*HDIM*HDIM + (size_t)o0*HDIM;
    const float*  wsE = g_wsEff + (t-1)*HDIM + o0;

    // ---- load resident B tile (128 x 512 int8) ----
    #pragma unroll
    for (int it = 0; it < 16; it++) {
        int f = it*256 + tid;
        int row = f >> 5, seg = f & 31;
        cpa16(dB + row*QSTR + seg*16, Bw8 + (size_t)row*HDIM + seg*16);
    }
    // ---- first A tile + first nm tile ----
    int curb = myStart >> 6;
    {
        const int8_t* A8 = g_q8[src] + (size_t)myStart * NROI * HDIM;
        #pragma unroll
        for (int it = 0; it < 8; it++) {
            int f = it*256 + tid;
            int row = f >> 5, seg = f & 31;
            cpa16(dA0 + row*QSTR + seg*16, A8 + (size_t)row*HDIM + seg*16);
        }
        const float* nmSrc = g_nm + ((size_t)curb*NROI)*HDIM + o0;
        #pragma unroll
        for (int it = 0; it < 8; it++) {
            int f = it*256 + tid;
            int row = f >> 5, seg = f & 31;
            cpa16(dNM + row*QSTR + seg*16, nmSrc + (size_t)row*HDIM + seg*4);
        }
    }
    asm volatile("cp.async.commit_group;");

    unsigned aOffW = (unsigned)((wm*16 + (lane & 15))*QSTR + (lane >> 4)*16);
    unsigned bBase = dB + (unsigned)((wn*64 + ((lane >> 4) << 3) + (lane & 7))*QSTR
                                     + ((lane >> 3) & 1)*16);

    int cur = 0;
    for (int ii = 0; ii < myCount; ii++) {
        int bi = myStart + ii;
        int b  = bi >> 6;

        // reload nm tile on b change (prev epilogue done reading old tile)
        if (b != curb) {
            __syncthreads();
            const float* nmSrc = g_nm + ((size_t)b*NROI)*HDIM + o0;
            #pragma unroll
            for (int it = 0; it < 8; it++) {
                int f = it*256 + tid;
                int row = f >> 5, seg = f & 31;
                cpa16(dNM + row*QSTR + seg*16, nmSrc + (size_t)row*HDIM + seg*4);
            }
            asm volatile("cp.async.commit_group;");
            curb = b;
        }

        asm volatile("cp.async.wait_group 0;");
        __syncthreads();

        // prefetch next bi's A into alt buffer
        if (ii + 1 < myCount) {
            unsigned dAn = (cur ^ 1) ? dA1 : dA0;
            const int8_t* An = g_q8[src] + (size_t)(bi+1) * NROI * HDIM;
            #pragma unroll
            for (int it = 0; it < 8; it++) {
                int f = it*256 + tid;
                int row = f >> 5, seg = f & 31;
                cpa16(dAn + row*QSTR + seg*16, An + (size_t)row*HDIM + seg*16);
            }
            asm volatile("cp.async.commit_group;");
        }

        // ---- int8 GEMM: 16 ksteps of 32 bytes, barrier-free ----
        unsigned dA = cur ? dA1 : dA0;
        int acc[8][4] = {};
        #pragma unroll
        for (int ks = 0; ks < 16; ks++) {
            unsigned a0,a1,a2,a3;
            asm volatile("ldmatrix.sync.aligned.m8n8.x4.shared.b16 {%0,%1,%2,%3},[%4];"
                : "=r"(a0),"=r"(a1),"=r"(a2),"=r"(a3) : "r"(dA + aOffW + (unsigned)(ks*32)));
            #pragma unroll
            for (int p2 = 0; p2 < 4; p2++) {
                unsigned b0,b1,b2,b3;
                asm volatile("ldmatrix.sync.aligned.m8n8.x4.shared.b16 {%0,%1,%2,%3},[%4];"
                    : "=r"(b0),"=r"(b1),"=r"(b2),"=r"(b3)
                    : "r"(bBase + (unsigned)(p2*16*QSTR + ks*32)));
                int* c0 = acc[p2*2];
                asm volatile("mma.sync.aligned.m16n8k32.row.col.s32.s8.s8.s32 "
                    "{%0,%1,%2,%3},{%4,%5,%6,%7},{%8,%9},{%0,%1,%2,%3};"
                    : "+r"(c0[0]),"+r"(c0[1]),"+r"(c0[2]),"+r"(c0[3])
                    : "r"(a0),"r"(a1),"r"(a2),"r"(a3),"r"(b0),"r"(b1));
                int* c1 = acc[p2*2+1];
                asm volatile("mma.sync.aligned.m16n8k32.row.col.s32.s8.s8.s32 "
                    "{%0,%1,%2,%3},{%4,%5,%6,%7},{%8,%9},{%0,%1,%2,%3};"
                    : "+r"(c1[0]),"+r"(c1[1]),"+r"(c1[2]),"+r"(c1[3])
                    : "r"(a0),"r"(a1),"r"(a2),"r"(a3),"r"(b2),"r"(b3));
            }
        }

        // ---- fused epilogue ----
        {
            int rbase = wm*16 + (lane >> 2);
            int j1 = rbase, j2 = rbase + 8;
            float m1 = (float)mask[bi*NROI + j1];
            float m2 = (float)mask[bi*NROI + j2];
            int iloc = bi & 63;
            int8_t* dstp = g_q8[dst] + (size_t)bi * NROI * HDIM;

            #pragma unroll
            for (int p = 0; p < 8; p++) {
                int oloc = wn*64 + p*8 + (lane & 3)*2;
                int o = o0 + oloc;
                float2 ws2 = *(const float2*)(wsE + oloc);
                float2 ebv = *(const float2*)(ebt + o);
                float2 ni, nj1, nj2;
                asm volatile("ld.shared.v2.f32 {%0,%1},[%2];" : "=f"(ni.x),"=f"(ni.y)
                    : "r"(dNM + iloc*QSTR + oloc*4));
                asm volatile("ld.shared.v2.f32 {%0,%1},[%2];" : "=f"(nj1.x),"=f"(nj1.y)
                    : "r"(dNM + j1*QSTR + oloc*4));
                asm volatile("ld.shared.v2.f32 {%0,%1},[%2];" : "=f"(nj2.x),"=f"(nj2.y)
                    : "r"(dNM + j2*QSTR + oloc*4));
                float bx = ni.x + ebv.x, by = ni.y + ebv.y;
                float e00 = leaky((float)acc[p][0]*ws2.x + bx + nj1.x);
                float e01 = leaky((float)acc[p][1]*ws2.y + by + nj1.y);
                float e10 = leaky((float)acc[p][2]*ws2.x + bx + nj2.x);
                float e11 = leaky((float)acc[p][3]*ws2.y + by + nj2.y);
                if (writeEdge) {
                    int q0 = q8clamp(e00*16.f) & 0xFF, q1 = q8clamp(e01*16.f) & 0xFF;
                    int q2 = q8clamp(e10*16.f) & 0xFF, q3 = q8clamp(e11*16.f) & 0xFF;
                    *(unsigned short*)(dstp + (size_t)j1*HDIM + o) = (unsigned short)(q0 | (q1<<8));
                    *(unsigned short*)(dstp + (size_t)j2*HDIM + o) = (unsigned short)(q2 | (q3<<8));
                }
                float s0 = e00*nj1.x*m1 + e10*nj2.x*m2;
                float s1 = e01*nj1.y*m1 + e11*nj2.y*m2;
                #pragma unroll
                for (int d = 4; d <= 16; d <<= 1) {
                    s0 += __shfl_xor_sync(0xffffffffu, s0, d);
                    s1 += __shfl_xor_sync(0xffffffffu, s1, d);
                }
                if (lane < 4) {
                    int oc = wn*64 + p*8 + lane*2;
                    aggsm[wm][oc]   = s0;
                    aggsm[wm][oc+1] = s1;
                }
            }
            __syncthreads();
            if (tid < 128) {
                float aggv = aggsm[0][tid] + aggsm[1][tid] + aggsm[2][tid] + aggsm[3][tid];
                int oo = o0 + tid;
                float nmv;
                asm volatile("ld.shared.f32 %0,[%1];" : "=f"(nmv)
                    : "r"(dNM + iloc*QSTR + tid*4));
                float x = (nmv + aggv) / g_denom[bi];
                float ns = g_ns[(size_t)bi*HDIM + oo] + leaky(x);
                g_ns[(size_t)bi*HDIM + oo] = ns;
                g_ns16[(size_t)bi*HDIM + oo] = __float2bfloat16(ns);
            }
            __syncthreads();
        }
        cur ^= 1;
    }
}

// ---------------- output: concat broadcast of node_state --------------------
__global__ void out_kernel(float* __restrict__ out) {
    size_t f = (size_t)blockIdx.x * blockDim.x + threadIdx.x;
    size_t total4 = (size_t)BSZ*NROI*NROI*1024 / 4;
    if (f >= total4) return;
    size_t flat = f * 4;
    int c = (int)(flat & 1023);
    size_t bij = flat >> 10;
    int j = (int)(bij & 63);
    size_t bi = bij >> 6;            // b*64+i
    size_t b  = bi >> 6;
    const float* src = (c < 512)
        ? (g_ns + bi * HDIM + c)
        : (g_ns + (b*64 + j) * HDIM + (c - 512));
    *(float4*)(out + flat) = *(const float4*)src;
}

// ---------------- host launch ------------------------------------------------
extern "C" void kernel_launch(void* const* d_in, const int* in_sizes, int n_in,
                              void* d_out, int out_size) {
    const float* roi = (const float*)d_in[0];
    const float* img = (const float*)d_in[1];
    const float* nW  = (const float*)d_in[2];
    const float* nb  = (const float*)d_in[3];
    const float* eW  = (const float*)d_in[4];
    const float* eb  = (const float*)d_in[5];
    const int*   msk = (const int*)d_in[6];
    float* out = (float*)d_out;

    cudaFuncSetAttribute(edge_q8_kernel,
                         cudaFuncAttributeMaxDynamicSharedMemorySize, EDSM8);

    prep_kernel<<<512, 256>>>(roi, img, msk);
    convW_kernel<<<(NLAYER*HDIM*HDIM/2 + 255)/256, 256>>>(nW);
    quantW_kernel<<<(4*HDIM*32 + 255)/256, 256>>>(eW);

    for (int t = 0; t < NLAYER; t++) {
        nm_mma_kernel<<<dim3(4, 8), 256>>>(t, nb + (size_t)t*HDIM);
        if (t == 0) {
            em0_kernel<<<512, 256>>>(eW, eb);
            edge0_kernel<<<512, 256>>>(msk);
        } else {
            int dst = t & 1;
            int src = dst ^ 1;
            int we  = (t < NLAYER - 1) ? 1 : 0;
            edge_q8_kernel<<<dim3(4, 37), 256, EDSM8>>>(
                t, eb + (size_t)t*HDIM, msk, src, dst, we);
        }
    }

    out_kernel<<<32768, 256>>>(out);
}

// round 9
// speedup vs baseline: 1.8204x; 1.8204x over previous
#include <cuda_runtime.h>
#include <cuda_bf16.h>
#include <cstdint>

#define BSZ   8
#define NROI  64
#define HDIM  512
#define NLAYER 5
#define BI    (BSZ*NROI)                     // 512 (b,i) pairs
#define NPAIR 2080                           // i<=j pairs
#define NPPAD 2112                           // 33*64 padded

// ---------------- scratch (device globals; no allocation allowed) ----------
__device__ __nv_bfloat16 g_ebuf[2][(size_t)BSZ*NPPAD*HDIM]; // symmetric edge_state, pair-compact
__device__ __nv_bfloat16 g_eW16[(size_t)NLAYER*HDIM*HDIM];  // bf16 edge weights
__device__ __nv_bfloat16 g_nW16[(size_t)NLAYER*HDIM*HDIM];  // bf16 node weights
__device__ __nv_bfloat16 g_ns16[BI*HDIM];               // bf16 mirror of node_state
__device__ float g_nm[BI*HDIM];
__device__ float g_ns[BI*HDIM];
__device__ float g_denom[BI];
__device__ float g_em0[BSZ*HDIM];                       // layer-0 edge matvec (incl. bias)
__device__ float g_e0[BSZ*HDIM];                        // mean of img_featmap
__device__ ushort2 g_pt[NPPAD];                         // pair p -> (i,j), i<=j

__device__ __forceinline__ float leaky(float x) { return x >= 0.f ? x : 0.01f * x; }
__device__ __forceinline__ unsigned smem_u32(const void* p) {
    return (unsigned)__cvta_generic_to_shared(p);
}
__device__ __forceinline__ void cpa16(unsigned dst, const void* src) {
    asm volatile("cp.async.ca.shared.global [%0], [%1], 16;" :: "r"(dst), "l"(src));
}

// ---------------- prep: node_state copy (+bf16), e0 mean, denom, pair table -
__global__ void prep_kernel(const float* __restrict__ roi,
                            const float* __restrict__ img,
                            const int*  __restrict__ mask) {
    int idx = blockIdx.x * blockDim.x + threadIdx.x;
    int total = blockDim.x * gridDim.x;
    for (int i = idx; i < BI*HDIM; i += total) {
        float v = roi[i];
        g_ns[i] = v;
        g_ns16[i] = __float2bfloat16(v);
    }
    if (idx < BSZ*HDIM) {
        const float* p = img + (size_t)idx * 196;
        float s = 0.f;
        #pragma unroll 4
        for (int q = 0; q < 196; q++) s += p[q];
        g_e0[idx] = s * (1.0f/196.0f);
    }
    if (idx < BI) {
        const int* m = mask + idx * NROI;
        int s = 0;
        #pragma unroll
        for (int j = 0; j < NROI; j++) s += m[j];
        g_denom[idx] = (float)s + 1.0f;
    }
    if (idx < NPPAD) {
        if (idx < NPAIR) {
            int p = idx, ii = 0;
            while (p >= NROI - ii) { p -= NROI - ii; ii++; }
            g_pt[idx] = make_ushort2((unsigned short)ii, (unsigned short)(ii + p));
        } else {
            g_pt[idx] = make_ushort2(0, 0);
        }
    }
}

// ---------------- convert edge + node weights to bf16 -----------------------
__global__ void convW_kernel(const float* __restrict__ eW,
                             const float* __restrict__ nW) {
    int i = blockIdx.x * blockDim.x + threadIdx.x;
    const int half = NLAYER*HDIM*HDIM/2;
    if (i < half) {
        float2 v = ((const float2*)eW)[i];
        ((__nv_bfloat162*)g_eW16)[i] = __floats2bfloat162_rn(v.x, v.y);
    } else if (i < 2*half) {
        float2 v = ((const float2*)nW)[i - half];
        ((__nv_bfloat162*)g_nW16)[i - half] = __floats2bfloat162_rn(v.x, v.y);
    }
}

// ---------------- layer-0 edge matvec (float4 vectorized) -------------------
__global__ void em0_kernel(const float* __restrict__ W0,
                           const float* __restrict__ eb0) {
    int warp = (blockIdx.x * blockDim.x + threadIdx.x) >> 5;
    int lane = threadIdx.x & 31;
    if (warp >= BSZ*HDIM) return;
    int b = warp >> 9;
    int o = warp & 511;
    const float4* e4 = (const float4*)(g_e0 + b*HDIM);
    const float4* w4 = (const float4*)(W0 + (size_t)o*HDIM);
    float s = 0.f;
    #pragma unroll
    for (int it = 0; it < 4; it++) {
        float4 e = e4[lane + it*32];
        float4 w = w4[lane + it*32];
        s += e.x*w.x + e.y*w.y + e.z*w.z + e.w*w.w;
    }
    #pragma unroll
    for (int d = 16; d; d >>= 1) s += __shfl_xor_sync(0xffffffffu, s, d);
    if (lane == 0) g_em0[warp] = s + eb0[o];
}

// ---------------- layer-0 edge state over pairs ------------------------------
// e0[b,p,o] = leaky(nm_i + nm_j + em0[b,o]), pair-compact write. grid (8,33).
__global__ void edge0_kernel() {
    int b  = blockIdx.x;
    int r0 = blockIdx.y * 64;
    int o  = threadIdx.x * 2;
    float2 em2 = *(const float2*)(g_em0 + b*HDIM + o);
    const float* nmb = g_nm + (size_t)b * NROI * HDIM;
    __nv_bfloat16* ebuf = g_ebuf[0] + (size_t)b * NPPAD * HDIM;
    #pragma unroll 4
    for (int r = 0; r < 64; r++) {
        ushort2 pj = g_pt[r0 + r];
        float2 ni = *(const float2*)(nmb + (size_t)pj.x*HDIM + o);
        float2 nj = *(const float2*)(nmb + (size_t)pj.y*HDIM + o);
        float e0 = leaky(ni.x + nj.x + em2.x);
        float e1 = leaky(ni.y + nj.y + em2.y);
        *(__nv_bfloat162*)(ebuf + (size_t)(r0 + r)*HDIM + o) = __floats2bfloat162_rn(e0, e1);
    }
}

// ---------------- agg + node update (per layer) ------------------------------
// agg[b,i,o] = sum_j e[pair(i,j)]*nm_j*mask[i,j]; ns += leaky((nm+agg)/denom).
__global__ void agg_node_kernel(int cur, const int* __restrict__ mask) {
    int bi = blockIdx.x;
    int b = bi >> 6, i = bi & 63;
    int o = threadIdx.x * 2;
    const float* nmb = g_nm + (size_t)b * NROI * HDIM;
    const __nv_bfloat16* ebuf = g_ebuf[cur] + (size_t)b * NPPAD * HDIM;
    int off_i = i*NROI - (i*(i-1))/2;
    float agg0 = 0.f, agg1 = 0.f;
    for (int j = 0; j < NROI; j++) {
        int p = (j >= i) ? (off_i + j - i)
                         : (j*NROI - (j*(j-1))/2 + i - j);
        __nv_bfloat162 e2 = *(const __nv_bfloat162*)(ebuf + (size_t)p*HDIM + o);
        float2 ef = __bfloat1622float2(e2);
        float m = (float)mask[bi*NROI + j];
        float2 nj = *(const float2*)(nmb + (size_t)j*HDIM + o);
        agg0 += ef.x * nj.x * m;
        agg1 += ef.y * nj.y * m;
    }
    float2 nmi = *(const float2*)(g_nm + (size_t)bi*HDIM + o);
    float dn = g_denom[bi];
    size_t base = (size_t)bi*HDIM + o;
    float ns0 = g_ns[base]     + leaky((nmi.x + agg0) / dn);
    float ns1 = g_ns[base + 1] + leaky((nmi.y + agg1) / dn);
    g_ns[base]     = ns0;
    g_ns[base + 1] = ns1;
    *(__nv_bfloat162*)(g_ns16 + base) = __floats2bfloat162_rn(ns0, ns1);
}

// ======================= shared GEMM params =================================
#define KC    32
#define NIT   (HDIM/KC)     // 16
#define STRD  40            // conflict-free smem stride (elems)

// ---------------- nm GEMM (bf16 MMA), 64x64 tiles, grid (8,8) ---------------
__global__ __launch_bounds__(256) void nm_mma_kernel(
    int t, const float* __restrict__ bt)
{
    __shared__ __nv_bfloat16 As[2][64*STRD];
    __shared__ __nv_bfloat16 Bs[2][64*STRD];

    int tid  = threadIdx.x;
    int wid  = tid >> 5, lane = tid & 31;
    int wm   = wid & 3, wn = wid >> 2;
    int r0   = blockIdx.y * 64;
    int o0   = blockIdx.x * 64;

    const __nv_bfloat16* A  = g_ns16 + (size_t)r0 * HDIM;
    const __nv_bfloat16* Bw = g_nW16 + (size_t)t * HDIM * HDIM + (size_t)o0 * HDIM;

    float acc[4][4] = {};

    int arow = tid >> 2, acol = (tid & 3) * 8;

    {
        cpa16(smem_u32(&As[0][arow*STRD + acol]), A + (size_t)arow*HDIM + acol);
        cpa16(smem_u32(&Bs[0][arow*STRD + acol]), Bw + (size_t)arow*HDIM + acol);
        asm volatile("cp.async.commit_group;");
    }

    for (int it = 0; it < NIT; it++) {
        asm volatile("cp.async.wait_group 0;");
        __syncthreads();
        if (it + 1 < NIT) {
            int st = (it + 1) & 1;
            int k0 = (it + 1) * KC;
            cpa16(smem_u32(&As[st][arow*STRD + acol]), A + (size_t)arow*HDIM + k0 + acol);
            cpa16(smem_u32(&Bs[st][arow*STRD + acol]), Bw + (size_t)arow*HDIM + k0 + acol);
            asm volatile("cp.async.commit_group;");
        }
        int st = it & 1;
        unsigned aBase = smem_u32(&As[st][(wm*16 + (lane & 15))*STRD + (lane >> 4)*8]);
        unsigned bBase = smem_u32(&Bs[st][(wn*32 + ((lane >> 4) << 3) + (lane & 7))*STRD
                                          + (((lane >> 3) & 1) << 3)]);
        #pragma unroll
        for (int ks = 0; ks < KC; ks += 16) {
            unsigned a0,a1,a2,a3;
            asm volatile("ldmatrix.sync.aligned.m8n8.x4.shared.b16 {%0,%1,%2,%3},[%4];"
                : "=r"(a0),"=r"(a1),"=r"(a2),"=r"(a3) : "r"(aBase + (unsigned)(ks*2)));
            #pragma unroll
            for (int p2 = 0; p2 < 2; p2++) {
                unsigned b0,b1,b2,b3;
                asm volatile("ldmatrix.sync.aligned.m8n8.x4.shared.b16 {%0,%1,%2,%3},[%4];"
                    : "=r"(b0),"=r"(b1),"=r"(b2),"=r"(b3)
                    : "r"(bBase + (unsigned)((p2*16*STRD + ks) * 2)));
                float* c0 = acc[p2*2];
                asm volatile("mma.sync.aligned.m16n8k16.row.col.f32.bf16.bf16.f32 "
                    "{%0,%1,%2,%3},{%4,%5,%6,%7},{%8,%9},{%0,%1,%2,%3};"
                    : "+f"(c0[0]),"+f"(c0[1]),"+f"(c0[2]),"+f"(c0[3])
                    : "r"(a0),"r"(a1),"r"(a2),"r"(a3),"r"(b0),"r"(b1));
                float* c1 = acc[p2*2+1];
                asm volatile("mma.sync.aligned.m16n8k16.row.col.f32.bf16.bf16.f32 "
                    "{%0,%1,%2,%3},{%4,%5,%6,%7},{%8,%9},{%0,%1,%2,%3};"
                    : "+f"(c1[0]),"+f"(c1[1]),"+f"(c1[2]),"+f"(c1[3])
                    : "r"(a0),"r"(a1),"r"(a2),"r"(a3),"r"(b2),"r"(b3));
            }
        }
        __syncthreads();
    }

    int r1 = r0 + wm*16 + (lane >> 2);
    int r2 = r1 + 8;
    #pragma unroll
    for (int p = 0; p < 4; p++) {
        int o = o0 + wn*32 + p*8 + (lane & 3)*2;
        float2 bo = *(const float2*)(bt + o);
        float2 v1; v1.x = acc[p][0] + bo.x; v1.y = acc[p][1] + bo.y;
        float2 v2; v2.x = acc[p][2] + bo.x; v2.y = acc[p][3] + bo.y;
        *(float2*)(g_nm + (size_t)r1*HDIM + o) = v1;
        *(float2*)(g_nm + (size_t)r2*HDIM + o) = v2;
    }
}

// ===== fused edge GEMM over symmetric pairs (layers 1..4) ===================
// Block: 64 pair-rows x 128 o. Grid (4 o-tiles, 33 row-blocks, 8 b).
// e[p,o] = leaky(em + nm_i + nm_j + eb), pair-compact bf16 write. Half FLOPs.
__global__ __launch_bounds__(256) void gemm_pairs_kernel(
    int t, const float* __restrict__ ebt, int src, int dst)
{
    __shared__ __nv_bfloat16 As[2][64*STRD];
    __shared__ __nv_bfloat16 Bs[2][128*STRD];

    int tid  = threadIdx.x;
    int wid  = tid >> 5, lane = tid & 31;
    int wm   = wid & 3, wn = wid >> 2;
    int b    = blockIdx.z;
    int r0   = blockIdx.y * 64;
    int o0   = blockIdx.x * 128;

    const __nv_bfloat16* A  = g_ebuf[src] + ((size_t)b * NPPAD + r0) * HDIM;
    const __nv_bfloat16* Bw = g_eW16 + (size_t)t * HDIM * HDIM + (size_t)o0 * HDIM;

    float acc[8][4] = {};

    int arow = tid >> 2, acol = (tid & 3) * 8;
    int brow = tid >> 1, bcol = (tid & 1) * 16;

    {
        cpa16(smem_u32(&As[0][arow*STRD + acol]), A + (size_t)arow*HDIM + acol);
        unsigned sB = smem_u32(&Bs[0][brow*STRD + bcol]);
        const __nv_bfloat16* gB = Bw + (size_t)brow*HDIM + bcol;
        cpa16(sB, gB); cpa16(sB+16, gB+8);
        asm volatile("cp.async.commit_group;");
    }

    for (int it = 0; it < NIT; it++) {
        asm volatile("cp.async.wait_group 0;");
        __syncthreads();
        if (it + 1 < NIT) {
            int st = (it + 1) & 1;
            int k0 = (it + 1) * KC;
            cpa16(smem_u32(&As[st][arow*STRD + acol]), A + (size_t)arow*HDIM + k0 + acol);
            unsigned sB = smem_u32(&Bs[st][brow*STRD + bcol]);
            const __nv_bfloat16* gB = Bw + (size_t)brow*HDIM + k0 + bcol;
            cpa16(sB, gB); cpa16(sB+16, gB+8);
            asm volatile("cp.async.commit_group;");
        }
        int st = it & 1;
        unsigned aBase = smem_u32(&As[st][(wm*16 + (lane & 15))*STRD + (lane >> 4)*8]);
        unsigned bBase = smem_u32(&Bs[st][(wn*64 + ((lane >> 4) << 3) + (lane & 7))*STRD
                                          + (((lane >> 3) & 1) << 3)]);
        #pragma unroll
        for (int ks = 0; ks < KC; ks += 16) {
            unsigned a0,a1,a2,a3;
            asm volatile("ldmatrix.sync.aligned.m8n8.x4.shared.b16 {%0,%1,%2,%3},[%4];"
                : "=r"(a0),"=r"(a1),"=r"(a2),"=r"(a3) : "r"(aBase + (unsigned)(ks*2)));
            #pragma unroll
            for (int p2 = 0; p2 < 4; p2++) {
                unsigned b0,b1,b2,b3;
                asm volatile("ldmatrix.sync.aligned.m8n8.x4.shared.b16 {%0,%1,%2,%3},[%4];"
                    : "=r"(b0),"=r"(b1),"=r"(b2),"=r"(b3)
                    : "r"(bBase + (unsigned)((p2*16*STRD + ks) * 2)));
                float* c0 = acc[p2*2];
                asm volatile("mma.sync.aligned.m16n8k16.row.col.f32.bf16.bf16.f32 "
                    "{%0,%1,%2,%3},{%4,%5,%6,%7},{%8,%9},{%0,%1,%2,%3};"
                    : "+f"(c0[0]),"+f"(c0[1]),"+f"(c0[2]),"+f"(c0[3])
                    : "r"(a0),"r"(a1),"r"(a2),"r"(a3),"r"(b0),"r"(b1));
                float* c1 = acc[p2*2+1];
                asm volatile("mma.sync.aligned.m16n8k16.row.col.f32.bf16.bf16.f32 "
                    "{%0,%1,%2,%3},{%4,%5,%6,%7},{%8,%9},{%0,%1,%2,%3};"
                    : "+f"(c1[0]),"+f"(c1[1]),"+f"(c1[2]),"+f"(c1[3])
                    : "r"(a0),"r"(a1),"r"(a2),"r"(a3),"r"(b2),"r"(b3));
            }
        }
        __syncthreads();
    }

    // ---- epilogue: leaky + pair-compact bf16 write ----
    int rbase = wm*16 + (lane >> 2);
    int r1 = rbase, r2 = rbase + 8;
    ushort2 pj1 = g_pt[r0 + r1];
    ushort2 pj2 = g_pt[r0 + r2];
    const float* nmb = g_nm + (size_t)b * NROI * HDIM;
    __nv_bfloat16* d1 = g_ebuf[dst] + ((size_t)b * NPPAD + r0 + r1) * HDIM;
    __nv_bfloat16* d2 = g_ebuf[dst] + ((size_t)b * NPPAD + r0 + r2) * HDIM;

    #pragma unroll
    for (int p = 0; p < 8; p++) {
        int o = o0 + wn*64 + p*8 + (lane & 3)*2;
        float2 ebv = *(const float2*)(ebt + o);
        float2 i1 = *(const float2*)(nmb + (size_t)pj1.x*HDIM + o);
        float2 j1 = *(const float2*)(nmb + (size_t)pj1.y*HDIM + o);
        float2 i2 = *(const float2*)(nmb + (size_t)pj2.x*HDIM + o);
        float2 j2 = *(const float2*)(nmb + (size_t)pj2.y*HDIM + o);
        float e00 = leaky(acc[p][0] + i1.x + j1.x + ebv.x);
        float e01 = leaky(acc[p][1] + i1.y + j1.y + ebv.y);
        float e10 = leaky(acc[p][2] + i2.x + j2.x + ebv.x);
        float e11 = leaky(acc[p][3] + i2.y + j2.y + ebv.y);
        *(__nv_bfloat162*)(d1 + o) = __floats2bfloat162_rn(e00, e01);
        *(__nv_bfloat162*)(d2 + o) = __floats2bfloat162_rn(e10, e11);
    }
}

// ---------------- output: concat broadcast of node_state --------------------
__global__ void out_kernel(float* __restrict__ out) {
    size_t f = (size_t)blockIdx.x * blockDim.x + threadIdx.x;
    size_t total4 = (size_t)BSZ*NROI*NROI*1024 / 4;
    if (f >= total4) return;
    size_t flat = f * 4;
    int c = (int)(flat & 1023);
    size_t bij = flat >> 10;
    int j = (int)(bij & 63);
    size_t bi = bij >> 6;            // b*64+i
    size_t b  = bi >> 6;
    const float* src = (c < 512)
        ? (g_ns + bi * HDIM + c)
        : (g_ns + (b*64 + j) * HDIM + (c - 512));
    *(float4*)(out + flat) = *(const float4*)src;
}

// ---------------- host launch ------------------------------------------------
extern "C" void kernel_launch(void* const* d_in, const int* in_sizes, int n_in,
                              void* d_out, int out_size) {
    const float* roi = (const float*)d_in[0];
    const float* img = (const float*)d_in[1];
    const float* nW  = (const float*)d_in[2];
    const float* nb  = (const float*)d_in[3];
    const float* eW  = (const float*)d_in[4];
    const float* eb  = (const float*)d_in[5];
    const int*   msk = (const int*)d_in[6];
    float* out = (float*)d_out;

    prep_kernel<<<512, 256>>>(roi, img, msk);
    convW_kernel<<<(NLAYER*HDIM*HDIM + 255)/256, 256>>>(eW, nW);

    for (int t = 0; t < NLAYER; t++) {
        nm_mma_kernel<<<dim3(8, 8), 256>>>(t, nb + (size_t)t*HDIM);
        if (t == 0) {
            em0_kernel<<<512, 256>>>(eW, eb);
            edge0_kernel<<<dim3(8, 33), 256>>>();
        } else {
            int dst = t & 1;
            int src = dst ^ 1;
            gemm_pairs_kernel<<<dim3(4, 33, 8), 256>>>(
                t, eb + (size_t)t*HDIM, src, dst);
        }
        agg_node_kernel<<<512, 256>>>(t & 1, msk);
    }

    out_kernel<<<32768, 256>>>(out);
}